// round 4
// baseline (speedup 1.0000x reference)
#include <cuda_runtime.h>

namespace {

constexpr int T = 2048;
constexpr int B = 4096;

typedef unsigned long long u64;

__device__ __forceinline__ u64 pack2(float lo, float hi) {
    u64 r; asm("mov.b64 %0,{%1,%2};" : "=l"(r) : "f"(lo), "f"(hi)); return r;
}
__device__ __forceinline__ void unpack2(u64 v, float& lo, float& hi) {
    asm("mov.b64 {%0,%1},%2;" : "=f"(lo), "=f"(hi) : "l"(v));
}
__device__ __forceinline__ u64 ffma2(u64 a, u64 b, u64 c) {
    u64 d; asm("fma.rn.f32x2 %0,%1,%2,%3;" : "=l"(d) : "l"(a), "l"(b), "l"(c)); return d;
}
__device__ __forceinline__ u64 fmul2(u64 a, u64 b) {
    u64 d; asm("mul.rn.f32x2 %0,%1,%2;" : "=l"(d) : "l"(a), "l"(b)); return d;
}
__device__ __forceinline__ float ex2a(float x) {
    float y; asm("ex2.approx.f32 %0,%1;" : "=f"(y) : "f"(x)); return y;
}
__device__ __forceinline__ float rcpa(float x) {
    float y; asm("rcp.approx.f32 %0,%1;" : "=f"(y) : "f"(x)); return y;
}
__device__ __forceinline__ float hadd(u64 v) {
    float lo, hi; unpack2(v, lo, hi); return lo + hi;
}

// 4 threads per batch chain. Thread q in {0..3} owns hidden units A=q, B=q+4.
// Accumulators are paired by h-terms: row g accumulates
//   low  half: sum_j W[g,j]   * h_j      (j = 0..3)
//   high half: sum_j W[g,j+4] * h_{j+4}
// with h-operand p_j = (h_j, h_{j+4}) delivered DIRECTLY by shfl — no splats.
// Gate scales (-log2e for r/z, -2*log2e for n) are folded into the weights so
// the activations are EX2+FADD+RCP with no pre-multiply.
__global__ void __launch_bounds__(128, 1) gru_fused_kernel(
    const float* __restrict__ x,
    const float* __restrict__ W_ih,
    const float* __restrict__ W_hh,
    const float* __restrict__ b_ih,
    const float* __restrict__ b_hh,
    const float* __restrict__ W_fc,
    const float* __restrict__ b_fc,
    float* __restrict__ out)
{
    const int tid = blockIdx.x * 128 + threadIdx.x;
    const int b = tid >> 2;
    const int q = tid & 3;

    const float SRZ = -1.4426950408889634f;   // -log2(e)
    const float SN  = -2.8853900817779268f;   // -2*log2(e)

    // ---- register-resident, pre-scaled weights ----
    u64 Wr[2][4], Wz[2][4], Wn[2][4];   // h-pair weights per (row A/B, j)
    u64 Xr[2][2], Xz[2][2], Xn[2][2];   // x-pair weights (pairs (x0,x2),(x1,x3))
    u64 Br[2], Bz[2], Bnx[2], Bnh[2];   // biases in low half
#pragma unroll
    for (int rr = 0; rr < 2; rr++) {
        const int gr = q + 4 * rr;
        const int gz = 8 + q + 4 * rr;
        const int gn = 16 + q + 4 * rr;
#pragma unroll
        for (int j = 0; j < 4; j++) {
            Wr[rr][j] = pack2(SRZ * W_hh[gr * 8 + j], SRZ * W_hh[gr * 8 + j + 4]);
            Wz[rr][j] = pack2(SRZ * W_hh[gz * 8 + j], SRZ * W_hh[gz * 8 + j + 4]);
            Wn[rr][j] = pack2(SN  * W_hh[gn * 8 + j], SN  * W_hh[gn * 8 + j + 4]);
        }
        Xr[rr][0] = pack2(SRZ * W_ih[gr * 4 + 0], SRZ * W_ih[gr * 4 + 2]);
        Xr[rr][1] = pack2(SRZ * W_ih[gr * 4 + 1], SRZ * W_ih[gr * 4 + 3]);
        Xz[rr][0] = pack2(SRZ * W_ih[gz * 4 + 0], SRZ * W_ih[gz * 4 + 2]);
        Xz[rr][1] = pack2(SRZ * W_ih[gz * 4 + 1], SRZ * W_ih[gz * 4 + 3]);
        Xn[rr][0] = pack2(SN  * W_ih[gn * 4 + 0], SN  * W_ih[gn * 4 + 2]);
        Xn[rr][1] = pack2(SN  * W_ih[gn * 4 + 1], SN  * W_ih[gn * 4 + 3]);
        Br[rr]  = pack2(SRZ * (b_ih[gr] + b_hh[gr]), 0.0f);
        Bz[rr]  = pack2(SRZ * (b_ih[gz] + b_hh[gz]), 0.0f);
        Bnx[rr] = pack2(SN * b_ih[gn], 0.0f);
        Bnh[rr] = pack2(SN * b_hh[gn], 0.0f);
    }
    u64 Wf[4];
#pragma unroll
    for (int j = 0; j < 4; j++)
        Wf[j] = pack2(W_fc[q * 8 + j], W_fc[q * 8 + j + 4]);
    const float bf = b_fc[q];

    const float4* xp = reinterpret_cast<const float4*>(x) + (size_t)b * T;
    float* op = out + (size_t)b * T * 4 + q;

    float hA = 0.0f, hB = 0.0f;           // owned hidden units
    u64 p0 = 0, p1 = 0, p2 = 0, p3 = 0;   // shfl'd pairs (h_j, h_{j+4})

    // 3-deep x prefetch pipeline (covers DRAM-miss latency on the 128B line)
    float4 xb0 = xp[0], xb1 = xp[1], xb2 = xp[2];

#pragma unroll 4
    for (int t = 0; t < T; t++) {
        float4 xc = xb0; xb0 = xb1; xb1 = xb2;
        int tn = t + 3; tn = (tn < T) ? tn : (T - 1);
        xb2 = xp[tn];

        // ---- emit y_{t-1} from p (h_{t-1}); dummy at t==0, overwritten ----
        {
            u64 ya = ffma2(Wf[0], p0, ffma2(Wf[1], p1, pack2(bf, 0.0f)));
            u64 yb = ffma2(Wf[2], p2, fmul2(Wf[3], p3));
            float yl, yh, yl2, yh2;
            unpack2(ya, yl, yh); unpack2(yb, yl2, yh2);
            int tp = t - (t > 0);
            op[tp * 4] = (yl + yh) + (yl2 + yh2);
        }

        // ---- x-side accumulators (independent of h; scheduled early) ----
        const u64 xq0 = pack2(xc.x, xc.z);
        const u64 xq1 = pack2(xc.y, xc.w);
        u64 aR[2], aZ[2], aNX[2], aNH[2];
#pragma unroll
        for (int rr = 0; rr < 2; rr++) {
            aR[rr]  = ffma2(Xr[rr][1], xq1, ffma2(Xr[rr][0], xq0, Br[rr]));
            aZ[rr]  = ffma2(Xz[rr][1], xq1, ffma2(Xz[rr][0], xq0, Bz[rr]));
            aNX[rr] = ffma2(Xn[rr][1], xq1, ffma2(Xn[rr][0], xq0, Bnx[rr]));
            aNH[rr] = Bnh[rr];
        }

        // ---- h-side: depth-4 FFMA2 chains fed directly by shfl pairs ----
#pragma unroll
        for (int rr = 0; rr < 2; rr++) {
            aR[rr]  = ffma2(Wr[rr][0], p0, aR[rr]);
            aR[rr]  = ffma2(Wr[rr][1], p1, aR[rr]);
            aR[rr]  = ffma2(Wr[rr][2], p2, aR[rr]);
            aR[rr]  = ffma2(Wr[rr][3], p3, aR[rr]);
            aZ[rr]  = ffma2(Wz[rr][0], p0, aZ[rr]);
            aZ[rr]  = ffma2(Wz[rr][1], p1, aZ[rr]);
            aZ[rr]  = ffma2(Wz[rr][2], p2, aZ[rr]);
            aZ[rr]  = ffma2(Wz[rr][3], p3, aZ[rr]);
            aNH[rr] = ffma2(Wn[rr][0], p0, aNH[rr]);
            aNH[rr] = ffma2(Wn[rr][1], p1, aNH[rr]);
            aNH[rr] = ffma2(Wn[rr][2], p2, aNH[rr]);
            aNH[rr] = ffma2(Wn[rr][3], p3, aNH[rr]);
        }

        // ---- activations (scales pre-folded: sigm = rcp(1+ex2(acc))) ----
        const float rA = rcpa(1.0f + ex2a(hadd(aR[0])));
        const float rB = rcpa(1.0f + ex2a(hadd(aR[1])));
        const float zA = rcpa(1.0f + ex2a(hadd(aZ[0])));
        const float zB = rcpa(1.0f + ex2a(hadd(aZ[1])));

        // v' = SN*(xn + r*hn); tanh(v) = 2*rcp(1+ex2(v')) - 1
        const float vA = fmaf(rA, hadd(aNH[0]), hadd(aNX[0]));
        const float vB = fmaf(rB, hadd(aNH[1]), hadd(aNX[1]));
        const float nA = fmaf(2.0f, rcpa(1.0f + ex2a(vA)), -1.0f);
        const float nB = fmaf(2.0f, rcpa(1.0f + ex2a(vB)), -1.0f);

        // ---- h = n*(1-z) + z*h : single FFMA after n arrives ----
        const float omzA = 1.0f - zA, omzB = 1.0f - zB;
        const float zhA = zA * hA,    zhB = zB * hB;
        hA = fmaf(nA, omzA, zhA);
        hB = fmaf(nB, omzB, zhB);

        // ---- broadcast: p_j = (h_j, h_{j+4}) straight from lanes ----
        p0 = pack2(__shfl_sync(0xffffffffu, hA, 0, 4), __shfl_sync(0xffffffffu, hB, 0, 4));
        p1 = pack2(__shfl_sync(0xffffffffu, hA, 1, 4), __shfl_sync(0xffffffffu, hB, 1, 4));
        p2 = pack2(__shfl_sync(0xffffffffu, hA, 2, 4), __shfl_sync(0xffffffffu, hB, 2, 4));
        p3 = pack2(__shfl_sync(0xffffffffu, hA, 3, 4), __shfl_sync(0xffffffffu, hB, 3, 4));
    }

    // ---- final y_{T-1} ----
    {
        u64 ya = ffma2(Wf[0], p0, ffma2(Wf[1], p1, pack2(bf, 0.0f)));
        u64 yb = ffma2(Wf[2], p2, fmul2(Wf[3], p3));
        float yl, yh, yl2, yh2;
        unpack2(ya, yl, yh); unpack2(yb, yl2, yh2);
        op[(T - 1) * 4] = (yl + yh) + (yl2 + yh2);
    }
}

} // namespace

extern "C" void kernel_launch(void* const* d_in, const int* in_sizes, int n_in,
                              void* d_out, int out_size)
{
    const float* x    = (const float*)d_in[0];
    const float* W_ih = (const float*)d_in[1];
    const float* W_hh = (const float*)d_in[2];
    const float* b_ih = (const float*)d_in[3];
    const float* b_hh = (const float*)d_in[4];
    const float* W_fc = (const float*)d_in[5];
    const float* b_fc = (const float*)d_in[6];
    float* out = (float*)d_out;

    // 4096 batches * 4 threads = 16384 threads; 128-thread blocks -> 128 blocks
    // (warps 0-3 map to SMSPs 0-3: one warp per SMSP, no scheduler contention)
    gru_fused_kernel<<<(B * 4) / 128, 128>>>(x, W_ih, W_hh, b_ih, b_hh, W_fc, b_fc, out);
}

// round 5
// speedup vs baseline: 1.0126x; 1.0126x over previous
#include <cuda_runtime.h>

namespace {

constexpr int T = 2048;
constexpr int B = 4096;
constexpr int BLK = 256;   // 8 warps/block -> 2 warps per SMSP on 64 SMs

typedef unsigned long long u64;

__device__ __forceinline__ u64 pack2(float lo, float hi) {
    u64 r; asm("mov.b64 %0,{%1,%2};" : "=l"(r) : "f"(lo), "f"(hi)); return r;
}
__device__ __forceinline__ void unpack2(u64 v, float& lo, float& hi) {
    asm("mov.b64 {%0,%1},%2;" : "=f"(lo), "=f"(hi) : "l"(v));
}
__device__ __forceinline__ u64 ffma2(u64 a, u64 b, u64 c) {
    u64 d; asm("fma.rn.f32x2 %0,%1,%2,%3;" : "=l"(d) : "l"(a), "l"(b), "l"(c)); return d;
}
__device__ __forceinline__ u64 fmul2(u64 a, u64 b) {
    u64 d; asm("mul.rn.f32x2 %0,%1,%2;" : "=l"(d) : "l"(a), "l"(b)); return d;
}
__device__ __forceinline__ float ex2a(float x) {
    float y; asm("ex2.approx.f32 %0,%1;" : "=f"(y) : "f"(x)); return y;
}
__device__ __forceinline__ float rcpa(float x) {
    float y; asm("rcp.approx.f32 %0,%1;" : "=f"(y) : "f"(x)); return y;
}
__device__ __forceinline__ float hadd(u64 v) {
    float lo, hi; unpack2(v, lo, hi); return lo + hi;
}

// 4 threads per batch chain. Thread q owns hidden units A=q, B=q+4, i.e. it
// natively holds the pair p_q = (h_q, h_{q+4}). Weight slots are ROTATED per
// thread (slot k <-> absolute h-index j=(q+k)&3) so slot 0 uses the local pair
// and only 3 foreign pairs arrive via 64-bit shfl (6 SASS SHFL/step).
// Gate scales (-log2e, -2log2e) folded into weights; activations are
// EX2 + FADD + RCP only.
__global__ void __launch_bounds__(BLK, 1) gru_fused_kernel(
    const float* __restrict__ x,
    const float* __restrict__ W_ih,
    const float* __restrict__ W_hh,
    const float* __restrict__ b_ih,
    const float* __restrict__ b_hh,
    const float* __restrict__ W_fc,
    const float* __restrict__ b_fc,
    float* __restrict__ out)
{
    const int tid = blockIdx.x * BLK + threadIdx.x;
    const int b = tid >> 2;
    const int q = tid & 3;

    const float SRZ = -1.4426950408889634f;   // -log2(e)
    const float SN  = -2.8853900817779268f;   // -2*log2(e)

    // ---- register-resident, pre-scaled, slot-rotated weights ----
    u64 Wr[2][4], Wz[2][4], Wn[2][4];   // [row A/B][slot k], k -> j=(q+k)&3
    u64 Xr[2][2], Xz[2][2], Xn[2][2];
    u64 Br[2], Bz[2], Bnx[2], Bnh[2];
#pragma unroll
    for (int rr = 0; rr < 2; rr++) {
        const int gr = q + 4 * rr;
        const int gz = 8 + q + 4 * rr;
        const int gn = 16 + q + 4 * rr;
#pragma unroll
        for (int k = 0; k < 4; k++) {
            const int j = (q + k) & 3;
            Wr[rr][k] = pack2(SRZ * W_hh[gr * 8 + j], SRZ * W_hh[gr * 8 + j + 4]);
            Wz[rr][k] = pack2(SRZ * W_hh[gz * 8 + j], SRZ * W_hh[gz * 8 + j + 4]);
            Wn[rr][k] = pack2(SN  * W_hh[gn * 8 + j], SN  * W_hh[gn * 8 + j + 4]);
        }
        Xr[rr][0] = pack2(SRZ * W_ih[gr * 4 + 0], SRZ * W_ih[gr * 4 + 2]);
        Xr[rr][1] = pack2(SRZ * W_ih[gr * 4 + 1], SRZ * W_ih[gr * 4 + 3]);
        Xz[rr][0] = pack2(SRZ * W_ih[gz * 4 + 0], SRZ * W_ih[gz * 4 + 2]);
        Xz[rr][1] = pack2(SRZ * W_ih[gz * 4 + 1], SRZ * W_ih[gz * 4 + 3]);
        Xn[rr][0] = pack2(SN  * W_ih[gn * 4 + 0], SN  * W_ih[gn * 4 + 2]);
        Xn[rr][1] = pack2(SN  * W_ih[gn * 4 + 1], SN  * W_ih[gn * 4 + 3]);
        Br[rr]  = pack2(SRZ * (b_ih[gr] + b_hh[gr]), 0.0f);
        Bz[rr]  = pack2(SRZ * (b_ih[gz] + b_hh[gz]), 0.0f);
        Bnx[rr] = pack2(SN * b_ih[gn], 0.0f);
        Bnh[rr] = pack2(SN * b_hh[gn], 0.0f);
    }
    u64 Wf[4];
#pragma unroll
    for (int k = 0; k < 4; k++) {
        const int j = (q + k) & 3;
        Wf[k] = pack2(W_fc[q * 8 + j], W_fc[q * 8 + j + 4]);
    }
    const u64 bfp = pack2(b_fc[q], 0.0f);

    const float4* xp = reinterpret_cast<const float4*>(x) + (size_t)b * T;
    float* op = out + (size_t)b * T * 4 + q;

    float hA = 0.0f, hB = 0.0f;
    u64 p0 = 0, p1 = 0, p2 = 0, p3 = 0;   // slot-k pairs; p0 is the local pair

    const int j1 = (q + 1) & 3, j2 = (q + 2) & 3, j3 = (q + 3) & 3;

    // 3-deep x prefetch pipeline
    float4 xb0 = xp[0], xb1 = xp[1], xb2 = xp[2];

#pragma unroll 2
    for (int t = 0; t < T; t++) {
        float4 xc = xb0; xb0 = xb1; xb1 = xb2;
        int tn = t + 3; tn = (tn < T) ? tn : (T - 1);
        xb2 = xp[tn];

        // ---- emit y_{t-1} from p (h_{t-1}); dummy at t==0, overwritten ----
        {
            u64 ya = ffma2(Wf[0], p0, ffma2(Wf[1], p1, bfp));
            u64 yb = ffma2(Wf[2], p2, fmul2(Wf[3], p3));
            float yl, yh, yl2, yh2;
            unpack2(ya, yl, yh); unpack2(yb, yl2, yh2);
            int tp = t - (t > 0);
            op[tp * 4] = (yl + yh) + (yl2 + yh2);
        }

        // ---- x-side accumulators (off the h-chain) ----
        const u64 xq0 = pack2(xc.x, xc.z);
        const u64 xq1 = pack2(xc.y, xc.w);
        u64 aR[2], aZ[2], aNX[2], aNH[2];
#pragma unroll
        for (int rr = 0; rr < 2; rr++) {
            aR[rr]  = ffma2(Xr[rr][1], xq1, ffma2(Xr[rr][0], xq0, Br[rr]));
            aZ[rr]  = ffma2(Xz[rr][1], xq1, ffma2(Xz[rr][0], xq0, Bz[rr]));
            aNX[rr] = ffma2(Xn[rr][1], xq1, ffma2(Xn[rr][0], xq0, Bnx[rr]));
            aNH[rr] = Bnh[rr];
        }

        // ---- h-side: depth-4 FFMA2 chains fed by shfl pairs ----
#pragma unroll
        for (int rr = 0; rr < 2; rr++) {
            aR[rr]  = ffma2(Wr[rr][0], p0, aR[rr]);
            aR[rr]  = ffma2(Wr[rr][1], p1, aR[rr]);
            aR[rr]  = ffma2(Wr[rr][2], p2, aR[rr]);
            aR[rr]  = ffma2(Wr[rr][3], p3, aR[rr]);
            aZ[rr]  = ffma2(Wz[rr][0], p0, aZ[rr]);
            aZ[rr]  = ffma2(Wz[rr][1], p1, aZ[rr]);
            aZ[rr]  = ffma2(Wz[rr][2], p2, aZ[rr]);
            aZ[rr]  = ffma2(Wz[rr][3], p3, aZ[rr]);
            aNH[rr] = ffma2(Wn[rr][0], p0, aNH[rr]);
            aNH[rr] = ffma2(Wn[rr][1], p1, aNH[rr]);
            aNH[rr] = ffma2(Wn[rr][2], p2, aNH[rr]);
            aNH[rr] = ffma2(Wn[rr][3], p3, aNH[rr]);
        }

        // ---- activations (scales pre-folded) ----
        const float rA = rcpa(1.0f + ex2a(hadd(aR[0])));
        const float rB = rcpa(1.0f + ex2a(hadd(aR[1])));
        const float zA = rcpa(1.0f + ex2a(hadd(aZ[0])));
        const float zB = rcpa(1.0f + ex2a(hadd(aZ[1])));

        const float vA = fmaf(rA, hadd(aNH[0]), hadd(aNX[0]));
        const float vB = fmaf(rB, hadd(aNH[1]), hadd(aNX[1]));
        const float nA = fmaf(2.0f, rcpa(1.0f + ex2a(vA)), -1.0f);
        const float nB = fmaf(2.0f, rcpa(1.0f + ex2a(vB)), -1.0f);

        // ---- h = n*(1-z) + z*h ----
        hA = fmaf(nA, 1.0f - zA, zA * hA);
        hB = fmaf(nB, 1.0f - zB, zB * hB);

        // ---- exchange: local pair + 3 foreign pairs via 64-bit shfl ----
        p0 = pack2(hA, hB);
        double hd = __longlong_as_double((long long)p0);
        p1 = (u64)__double_as_longlong(__shfl_sync(0xffffffffu, hd, j1, 4));
        p2 = (u64)__double_as_longlong(__shfl_sync(0xffffffffu, hd, j2, 4));
        p3 = (u64)__double_as_longlong(__shfl_sync(0xffffffffu, hd, j3, 4));
    }

    // ---- final y_{T-1} ----
    {
        u64 ya = ffma2(Wf[0], p0, ffma2(Wf[1], p1, bfp));
        u64 yb = ffma2(Wf[2], p2, fmul2(Wf[3], p3));
        float yl, yh, yl2, yh2;
        unpack2(ya, yl, yh); unpack2(yb, yl2, yh2);
        op[(T - 1) * 4] = (yl + yh) + (yl2 + yh2);
    }
}

} // namespace

extern "C" void kernel_launch(void* const* d_in, const int* in_sizes, int n_in,
                              void* d_out, int out_size)
{
    const float* x    = (const float*)d_in[0];
    const float* W_ih = (const float*)d_in[1];
    const float* W_hh = (const float*)d_in[2];
    const float* b_ih = (const float*)d_in[3];
    const float* b_hh = (const float*)d_in[4];
    const float* W_fc = (const float*)d_in[5];
    const float* b_fc = (const float*)d_in[6];
    float* out = (float*)d_out;

    // 16384 threads as 64 blocks x 256: 8 warps/SM on 64 SMs = 2 warps/SMSP,
    // so each warp's latency bubbles are filled by its sibling warp.
    gru_fused_kernel<<<(B * 4) / BLK, BLK>>>(x, W_ih, W_hh, b_ih, b_hh, W_fc, b_fc, out);
}

// round 6
// speedup vs baseline: 1.3209x; 1.3045x over previous
#include <cuda_runtime.h>

namespace {

constexpr int T = 2048;
constexpr int B = 4096;
constexpr int BLK = 256;   // 8 warps/block -> 2 warps per SMSP on 64 SMs

typedef unsigned long long u64;

__device__ __forceinline__ u64 pack2(float lo, float hi) {
    u64 r; asm("mov.b64 %0,{%1,%2};" : "=l"(r) : "f"(lo), "f"(hi)); return r;
}
__device__ __forceinline__ void unpack2(u64 v, float& lo, float& hi) {
    asm("mov.b64 {%0,%1},%2;" : "=f"(lo), "=f"(hi) : "l"(v));
}
__device__ __forceinline__ u64 ffma2(u64 a, u64 b, u64 c) {
    u64 d; asm("fma.rn.f32x2 %0,%1,%2,%3;" : "=l"(d) : "l"(a), "l"(b), "l"(c)); return d;
}
__device__ __forceinline__ u64 fmul2(u64 a, u64 b) {
    u64 d; asm("mul.rn.f32x2 %0,%1,%2;" : "=l"(d) : "l"(a), "l"(b)); return d;
}
__device__ __forceinline__ float tanha(float x) {
    float y; asm("tanh.approx.f32 %0,%1;" : "=f"(y) : "f"(x)); return y;
}
__device__ __forceinline__ float hadd(u64 v) {
    float lo, hi; unpack2(v, lo, hi); return lo + hi;
}

// 4 threads per batch chain. Thread q owns hidden units A=q, B=q+4 and thus
// natively holds the pair p_q = (h_q, h_{q+4}); weight slots are rotated per
// thread (slot k <-> j=(q+k)&3) so only 3 foreign pairs arrive via shfl.
// Activations via MUFU.TANH: sigmoid(u) = 0.5 + 0.5*tanh(u/2) with the 1/2
// folded into r/z weights at init; n = tanh(v) directly (no scale folding).
__global__ void __launch_bounds__(BLK, 1) gru_fused_kernel(
    const float* __restrict__ x,
    const float* __restrict__ W_ih,
    const float* __restrict__ W_hh,
    const float* __restrict__ b_ih,
    const float* __restrict__ b_hh,
    const float* __restrict__ W_fc,
    const float* __restrict__ b_fc,
    float* __restrict__ out)
{
    const int tid = blockIdx.x * BLK + threadIdx.x;
    const int b = tid >> 2;
    const int q = tid & 3;

    const float HS = 0.5f;   // gate pre-activation scale for tanh-sigmoid

    // ---- register-resident, pre-scaled, slot-rotated weights ----
    u64 Wr[2][4], Wz[2][4], Wn[2][4];   // [row A/B][slot k], k -> j=(q+k)&3
    u64 Xr[2][2], Xz[2][2], Xn[2][2];
    u64 Br[2], Bz[2], Bnx[2], Bnh[2];
#pragma unroll
    for (int rr = 0; rr < 2; rr++) {
        const int gr = q + 4 * rr;
        const int gz = 8 + q + 4 * rr;
        const int gn = 16 + q + 4 * rr;
#pragma unroll
        for (int k = 0; k < 4; k++) {
            const int j = (q + k) & 3;
            Wr[rr][k] = pack2(HS * W_hh[gr * 8 + j], HS * W_hh[gr * 8 + j + 4]);
            Wz[rr][k] = pack2(HS * W_hh[gz * 8 + j], HS * W_hh[gz * 8 + j + 4]);
            Wn[rr][k] = pack2(W_hh[gn * 8 + j], W_hh[gn * 8 + j + 4]);
        }
        Xr[rr][0] = pack2(HS * W_ih[gr * 4 + 0], HS * W_ih[gr * 4 + 2]);
        Xr[rr][1] = pack2(HS * W_ih[gr * 4 + 1], HS * W_ih[gr * 4 + 3]);
        Xz[rr][0] = pack2(HS * W_ih[gz * 4 + 0], HS * W_ih[gz * 4 + 2]);
        Xz[rr][1] = pack2(HS * W_ih[gz * 4 + 1], HS * W_ih[gz * 4 + 3]);
        Xn[rr][0] = pack2(W_ih[gn * 4 + 0], W_ih[gn * 4 + 2]);
        Xn[rr][1] = pack2(W_ih[gn * 4 + 1], W_ih[gn * 4 + 3]);
        Br[rr]  = pack2(HS * (b_ih[gr] + b_hh[gr]), 0.0f);
        Bz[rr]  = pack2(HS * (b_ih[gz] + b_hh[gz]), 0.0f);
        Bnx[rr] = pack2(b_ih[gn], 0.0f);
        Bnh[rr] = pack2(b_hh[gn], 0.0f);
    }
    u64 Wf[4];
#pragma unroll
    for (int k = 0; k < 4; k++) {
        const int j = (q + k) & 3;
        Wf[k] = pack2(W_fc[q * 8 + j], W_fc[q * 8 + j + 4]);
    }
    const u64 bfp = pack2(b_fc[q], 0.0f);

    const float4* xp = reinterpret_cast<const float4*>(x) + (size_t)b * T;
    float* op = out + (size_t)b * T * 4 + q;

    float hA = 0.0f, hB = 0.0f;
    u64 p0 = 0, p1 = 0, p2 = 0, p3 = 0;   // slot-k pairs; p0 is the local pair

    const int j1 = (q + 1) & 3, j2 = (q + 2) & 3, j3 = (q + 3) & 3;

    // 3-deep x prefetch pipeline
    float4 xb0 = xp[0], xb1 = xp[1], xb2 = xp[2];

#pragma unroll 2
    for (int t = 0; t < T; t++) {
        float4 xc = xb0; xb0 = xb1; xb1 = xb2;
        int tn = t + 3; tn = (tn < T) ? tn : (T - 1);
        xb2 = xp[tn];

        // ---- emit y_{t-1} from p (h_{t-1}); dummy at t==0, overwritten ----
        {
            u64 ya = ffma2(Wf[0], p0, ffma2(Wf[1], p1, bfp));
            u64 yb = ffma2(Wf[2], p2, fmul2(Wf[3], p3));
            float yl, yh, yl2, yh2;
            unpack2(ya, yl, yh); unpack2(yb, yl2, yh2);
            int tp = t - (t > 0);
            op[tp * 4] = (yl + yh) + (yl2 + yh2);
        }

        // ---- x-side accumulators (off the h-chain) ----
        const u64 xq0 = pack2(xc.x, xc.z);
        const u64 xq1 = pack2(xc.y, xc.w);
        u64 aR[2], aZ[2], aNX[2], aNH[2];
#pragma unroll
        for (int rr = 0; rr < 2; rr++) {
            aR[rr]  = ffma2(Xr[rr][1], xq1, ffma2(Xr[rr][0], xq0, Br[rr]));
            aZ[rr]  = ffma2(Xz[rr][1], xq1, ffma2(Xz[rr][0], xq0, Bz[rr]));
            aNX[rr] = ffma2(Xn[rr][1], xq1, ffma2(Xn[rr][0], xq0, Bnx[rr]));
            aNH[rr] = Bnh[rr];
        }

        // ---- h-side: depth-4 FFMA2 chains fed by shfl pairs ----
#pragma unroll
        for (int rr = 0; rr < 2; rr++) {
            aR[rr]  = ffma2(Wr[rr][0], p0, aR[rr]);
            aR[rr]  = ffma2(Wr[rr][1], p1, aR[rr]);
            aR[rr]  = ffma2(Wr[rr][2], p2, aR[rr]);
            aR[rr]  = ffma2(Wr[rr][3], p3, aR[rr]);
            aZ[rr]  = ffma2(Wz[rr][0], p0, aZ[rr]);
            aZ[rr]  = ffma2(Wz[rr][1], p1, aZ[rr]);
            aZ[rr]  = ffma2(Wz[rr][2], p2, aZ[rr]);
            aZ[rr]  = ffma2(Wz[rr][3], p3, aZ[rr]);
            aNH[rr] = ffma2(Wn[rr][0], p0, aNH[rr]);
            aNH[rr] = ffma2(Wn[rr][1], p1, aNH[rr]);
            aNH[rr] = ffma2(Wn[rr][2], p2, aNH[rr]);
            aNH[rr] = ffma2(Wn[rr][3], p3, aNH[rr]);
        }

        // ---- activations via MUFU.TANH ----
        // r/z: acc already = u/2 (weights pre-halved); sigm = 0.5 + 0.5*tanh
        const float rA = fmaf(0.5f, tanha(hadd(aR[0])), 0.5f);
        const float rB = fmaf(0.5f, tanha(hadd(aR[1])), 0.5f);
        const float zA = fmaf(0.5f, tanha(hadd(aZ[0])), 0.5f);
        const float zB = fmaf(0.5f, tanha(hadd(aZ[1])), 0.5f);

        const float vA = fmaf(rA, hadd(aNH[0]), hadd(aNX[0]));
        const float vB = fmaf(rB, hadd(aNH[1]), hadd(aNX[1]));
        const float nA = tanha(vA);
        const float nB = tanha(vB);

        // ---- h = n + z*(h - n) ----
        hA = fmaf(zA, hA - nA, nA);
        hB = fmaf(zB, hB - nB, nB);

        // ---- exchange: local pair + 3 foreign pairs via 64-bit shfl ----
        p0 = pack2(hA, hB);
        double hd = __longlong_as_double((long long)p0);
        p1 = (u64)__double_as_longlong(__shfl_sync(0xffffffffu, hd, j1, 4));
        p2 = (u64)__double_as_longlong(__shfl_sync(0xffffffffu, hd, j2, 4));
        p3 = (u64)__double_as_longlong(__shfl_sync(0xffffffffu, hd, j3, 4));
    }

    // ---- final y_{T-1} ----
    {
        u64 ya = ffma2(Wf[0], p0, ffma2(Wf[1], p1, bfp));
        u64 yb = ffma2(Wf[2], p2, fmul2(Wf[3], p3));
        float yl, yh, yl2, yh2;
        unpack2(ya, yl, yh); unpack2(yb, yl2, yh2);
        op[(T - 1) * 4] = (yl + yh) + (yl2 + yh2);
    }
}

} // namespace

extern "C" void kernel_launch(void* const* d_in, const int* in_sizes, int n_in,
                              void* d_out, int out_size)
{
    const float* x    = (const float*)d_in[0];
    const float* W_ih = (const float*)d_in[1];
    const float* W_hh = (const float*)d_in[2];
    const float* b_ih = (const float*)d_in[3];
    const float* b_hh = (const float*)d_in[4];
    const float* W_fc = (const float*)d_in[5];
    const float* b_fc = (const float*)d_in[6];
    float* out = (float*)d_out;

    // 16384 threads as 64 blocks x 256: 2 warps per SMSP on 64 SMs —
    // sibling warp fills issue bubbles; body shrunk via MUFU.TANH.
    gru_fused_kernel<<<(B * 4) / BLK, BLK>>>(x, W_ih, W_hh, b_ih, b_hh, W_fc, b_fc, out);
}